// round 1
// baseline (speedup 1.0000x reference)
#include <cuda_runtime.h>
#include <math.h>

// Problem constants (fixed shapes)
#define Bb   16
#define Ss   4096
#define Hh   12
#define Dd   64
constexpr int M = Bb * Ss;   // 65536 rows
constexpr int N = 768;       // QKV / HID
constexpr int K = 768;

// Scratch (device globals — allocation-free per harness rules)
__device__ float g_q[(size_t)M * N];
__device__ float g_k[(size_t)M * N];
__device__ float g_v[(size_t)M * N];
__device__ float g_attn[(size_t)M * N];
__device__ float g_kv[Bb * Hh * Dd * Dd];
__device__ float g_ksum[Bb * Hh * Dd];

// ---------------------------------------------------------------------------
// Generic 128x128x8 fp32 SGEMM with fused epilogue.
// epi = 0 : C = A*W + bias                      (output projection)
// epi = 1 : C = (A*W + bias) * mask             (V)
// epi = 2 : C = lka((A*W + bias) * mask) * 1/8  (Q, K)  lka(x)=elu(x)+1
// ---------------------------------------------------------------------------
__global__ void __launch_bounds__(256, 2)
gemm768(const float* __restrict__ A, const float* __restrict__ W,
        const float* __restrict__ bias, const float* __restrict__ mask,
        float* __restrict__ C, int epi)
{
    constexpr int BM = 128, BN = 128, BK = 8, TM = 8, TN = 8;
    __shared__ float As[BK][BM];
    __shared__ float Bs[BK][BN];

    const int tid  = threadIdx.x;
    const int cRow = blockIdx.y;   // M tile
    const int cCol = blockIdx.x;   // N tile

    const int tCol = tid & 15;     // 0..15
    const int tRow = tid >> 4;     // 0..15

    // load mapping
    const int aRow = tid >> 1;          // 0..127
    const int aCol = (tid & 1) * 4;     // 0 or 4
    const int bRow = tid >> 5;          // 0..7
    const int bCol = (tid & 31) * 4;    // 0..124

    const float* Ab = A + (size_t)cRow * BM * K;
    const float* Wb = W + cCol * BN;

    float acc[TM][TN] = {};
    float rM[TM], rN[TN];

    for (int k0 = 0; k0 < K; k0 += BK) {
        float4 a4 = *reinterpret_cast<const float4*>(Ab + (size_t)aRow * K + k0 + aCol);
        As[aCol + 0][aRow] = a4.x;
        As[aCol + 1][aRow] = a4.y;
        As[aCol + 2][aRow] = a4.z;
        As[aCol + 3][aRow] = a4.w;
        float4 b4 = *reinterpret_cast<const float4*>(Wb + (size_t)(k0 + bRow) * N + bCol);
        *reinterpret_cast<float4*>(&Bs[bRow][bCol]) = b4;
        __syncthreads();

        #pragma unroll
        for (int kk = 0; kk < BK; kk++) {
            #pragma unroll
            for (int i = 0; i < TM; i++) rM[i] = As[kk][tRow * TM + i];
            #pragma unroll
            for (int j = 0; j < TN; j++) rN[j] = Bs[kk][tCol * TN + j];
            #pragma unroll
            for (int i = 0; i < TM; i++)
                #pragma unroll
                for (int j = 0; j < TN; j++)
                    acc[i][j] = fmaf(rM[i], rN[j], acc[i][j]);
        }
        __syncthreads();
    }

    #pragma unroll
    for (int i = 0; i < TM; i++) {
        const int m = cRow * BM + tRow * TM + i;
        const float mk = (epi >= 1) ? mask[m] : 1.0f;
        #pragma unroll
        for (int j = 0; j < TN; j++) {
            const int n = cCol * BN + tCol * TN + j;
            float v = acc[i][j] + bias[n];
            if (epi >= 1) v *= mk;
            if (epi == 2) {
                v = (v > 0.0f) ? (v + 1.0f) : expf(v);   // elu(x)+1
                v *= 0.125f;                             // 1/sqrt(64)
            }
            C[(size_t)m * N + n] = v;
        }
    }
}

// ---------------------------------------------------------------------------
// Per-(b,h): kv[d][e] = sum_s k[s][d]*v[s][e]  and  ksum[d] = sum_s k[s][d]
// grid = B*H blocks, 256 threads. Each thread owns 1 d-row x 16 e-cols of kv.
// ---------------------------------------------------------------------------
__global__ void __launch_bounds__(256)
kv_ksum_kernel(const float* __restrict__ Kf, const float* __restrict__ Vf)
{
    __shared__ float Ks[64][64];
    __shared__ float Vs[64][64];

    const int bh = blockIdx.x;
    const int b = bh / Hh, h = bh % Hh;
    const int tid = threadIdx.x;
    const int d  = tid >> 2;          // 0..63
    const int e0 = (tid & 3) * 16;    // 0,16,32,48

    float acc[16] = {};
    float ks = 0.0f;

    for (int s0 = 0; s0 < Ss; s0 += 64) {
        #pragma unroll
        for (int i = 0; i < 4; i++) {
            const int lin = tid + i * 256;       // 0..1023 float4 slots
            const int r = lin >> 4;
            const int c = (lin & 15) * 4;
            const size_t off = ((size_t)(b * Ss + s0 + r)) * 768 + h * 64 + c;
            *reinterpret_cast<float4*>(&Ks[r][c]) = *reinterpret_cast<const float4*>(Kf + off);
            *reinterpret_cast<float4*>(&Vs[r][c]) = *reinterpret_cast<const float4*>(Vf + off);
        }
        __syncthreads();

        #pragma unroll 4
        for (int s = 0; s < 64; s++) {
            const float kval = Ks[s][d];
            #pragma unroll
            for (int j = 0; j < 16; j++)
                acc[j] = fmaf(kval, Vs[s][e0 + j], acc[j]);
        }
        if (tid < 64) {
            #pragma unroll 4
            for (int s = 0; s < 64; s++) ks += Ks[s][tid];
        }
        __syncthreads();
    }

    const size_t base = ((size_t)bh * 64 + d) * 64 + e0;
    #pragma unroll
    for (int j = 0; j < 16; j++) g_kv[base + j] = acc[j];
    if (tid < 64) g_ksum[bh * 64 + tid] = ks;
}

// ---------------------------------------------------------------------------
// Per-(b,h): out[s][e] = (sum_d q[s][d]*kv[d][e]) / (sum_d q[s][d]*ksum[d])
// grid = (B*H, S/64), 256 threads; each pass handles 4 s-rows x 64 e.
// ---------------------------------------------------------------------------
__global__ void __launch_bounds__(256)
attn_apply_kernel(const float* __restrict__ Q, float* __restrict__ Out)
{
    __shared__ float kvS[64][64];
    __shared__ float ksS[64];
    __shared__ float qS[4][64];

    const int bh = blockIdx.x;
    const int b = bh / Hh, h = bh % Hh;
    const int tid = threadIdx.x;

    #pragma unroll
    for (int i = 0; i < 4; i++) {
        const int lin = tid + i * 256;
        const int r = lin >> 4;
        const int c = (lin & 15) * 4;
        *reinterpret_cast<float4*>(&kvS[r][c]) =
            *reinterpret_cast<const float4*>(&g_kv[((size_t)bh * 64 + r) * 64 + c]);
    }
    if (tid < 16)
        *reinterpret_cast<float4*>(&ksS[tid * 4]) =
            *reinterpret_cast<const float4*>(&g_ksum[bh * 64 + tid * 4]);
    __syncthreads();

    const int e  = tid & 63;
    const int rr = tid >> 6;  // 0..3

    for (int it = 0; it < 16; it++) {
        const int s = blockIdx.y * 64 + it * 4 + rr;
        const size_t rowoff = ((size_t)(b * Ss + s)) * 768 + h * 64;
        qS[rr][e] = Q[rowoff + e];
        __syncthreads();

        float num = 0.0f, den = 0.0f;
        #pragma unroll
        for (int dd = 0; dd < 64; dd++) {
            const float qv = qS[rr][dd];
            num = fmaf(qv, kvS[dd][e], num);
            den = fmaf(qv, ksS[dd], den);
        }
        Out[rowoff + e] = num / den;
        __syncthreads();
    }
}

// ---------------------------------------------------------------------------
extern "C" void kernel_launch(void* const* d_in, const int* in_sizes, int n_in,
                              void* d_out, int out_size)
{
    const float* x    = (const float*)d_in[0];
    const float* mask = (const float*)d_in[1];
    const float* Wq   = (const float*)d_in[2];
    const float* bq   = (const float*)d_in[3];
    const float* Wk   = (const float*)d_in[4];
    const float* bk   = (const float*)d_in[5];
    const float* Wv   = (const float*)d_in[6];
    const float* bv   = (const float*)d_in[7];
    const float* Wo   = (const float*)d_in[8];
    const float* bo   = (const float*)d_in[9];
    float* out = (float*)d_out;

    float *qp, *kp, *vp, *ap;
    cudaGetSymbolAddress((void**)&qp, g_q);
    cudaGetSymbolAddress((void**)&kp, g_k);
    cudaGetSymbolAddress((void**)&vp, g_v);
    cudaGetSymbolAddress((void**)&ap, g_attn);

    const dim3 grid(N / 128, M / 128);  // (6, 512)

    gemm768<<<grid, 256>>>(x, Wq, bq, mask, qp, 2);
    gemm768<<<grid, 256>>>(x, Wk, bk, mask, kp, 2);
    gemm768<<<grid, 256>>>(x, Wv, bv, mask, vp, 1);

    kv_ksum_kernel<<<Bb * Hh, 256>>>(kp, vp);
    attn_apply_kernel<<<dim3(Bb * Hh, Ss / 64), 256>>>(qp, ap);

    gemm768<<<grid, 256>>>(ap, Wo, bo, mask, out, 0);
}

// round 3
// speedup vs baseline: 2.2256x; 2.2256x over previous
#include <cuda_runtime.h>
#include <cuda_bf16.h>
#include <math.h>
#include <stdint.h>

// Problem constants
#define Bb   16
#define Ss   4096
#define Hh   12
#define Dd   64
constexpr int M = Bb * Ss;   // 65536
constexpr int N = 768;
constexpr int K = 768;

// ---------------------------------------------------------------------------
// Scratch (device globals)
// ---------------------------------------------------------------------------
__device__ float g_q[(size_t)M * N];
__device__ float g_k[(size_t)M * N];
__device__ float g_v[(size_t)M * N];
__device__ __nv_bfloat16 g_xhi[(size_t)M * N];
__device__ __nv_bfloat16 g_xlo[(size_t)M * N];
__device__ __nv_bfloat16 g_ahi[(size_t)M * N];
__device__ __nv_bfloat16 g_alo[(size_t)M * N];
__device__ __nv_bfloat16 g_whi[4][768 * 768];
__device__ __nv_bfloat16 g_wlo[4][768 * 768];
__device__ float g_kv[Bb * Hh * Dd * Dd];
__device__ float g_ksum[Bb * Hh * Dd];

// ---------------------------------------------------------------------------
// PTX helpers (sm_80-compatible only: cp.async, ldmatrix, mma.sync)
// ---------------------------------------------------------------------------
__device__ __forceinline__ uint32_t smem_u32(const void* p) {
    uint32_t a;
    asm("{ .reg .u64 t; cvta.to.shared.u64 t, %1; cvt.u32.u64 %0, t; }"
        : "=r"(a) : "l"(p));
    return a;
}

__device__ __forceinline__ void cpa16(uint32_t dst, const void* src) {
    asm volatile("cp.async.cg.shared.global [%0], [%1], 16;" :: "r"(dst), "l"(src) : "memory");
}
#define CP_COMMIT() asm volatile("cp.async.commit_group;" ::: "memory")
#define CP_WAIT(n)  asm volatile("cp.async.wait_group %0;" :: "n"(n) : "memory")

__device__ __forceinline__ void ldsm4(uint32_t* r, uint32_t addr) {
    asm volatile("ldmatrix.sync.aligned.m8n8.x4.shared.b16 {%0,%1,%2,%3}, [%4];"
                 : "=r"(r[0]), "=r"(r[1]), "=r"(r[2]), "=r"(r[3]) : "r"(addr));
}

__device__ __forceinline__ void mma_bf16(float* c, const uint32_t* a, const uint32_t* b) {
    asm volatile(
        "mma.sync.aligned.m16n8k16.row.col.f32.bf16.bf16.f32 "
        "{%0,%1,%2,%3}, {%4,%5,%6,%7}, {%8,%9}, {%0,%1,%2,%3};"
        : "+f"(c[0]), "+f"(c[1]), "+f"(c[2]), "+f"(c[3])
        : "r"(a[0]), "r"(a[1]), "r"(a[2]), "r"(a[3]), "r"(b[0]), "r"(b[1]));
}

// ---------------------------------------------------------------------------
// bf16-split GEMM via mma.sync:
//   C[M,768] = (Ahi+Alo)[M,768] x (Whi+Wlo)^T     (W pre-transposed: Bt[n][k])
// CTA tile 128x128, BK=32, double-buffered cp.async.
// Smem per stage: Ahi(8K) Alo(8K) Bhi(8K) Blo(8K) = 32KB. XOR swizzle on 16B
// chunks: sc = c ^ ((row>>1)&3)  (row stride 64B, 4 chunks/row).
// epi: 0 = +bias; 1 = (+bias)*mask; 2 = lka((+bias)*mask)/8
// ---------------------------------------------------------------------------
constexpr int STAGE_BYTES = 32768;
constexpr int GSMEM_BYTES = 2 * STAGE_BYTES;

__device__ __forceinline__ void stage_load(
    uint32_t sbase,
    const __nv_bfloat16* __restrict__ Ahi, const __nv_bfloat16* __restrict__ Alo,
    const __nv_bfloat16* __restrict__ Bhi, const __nv_bfloat16* __restrict__ Blo,
    int mb, int nb, int k0, int tid)
{
    #pragma unroll
    for (int t = 0; t < 2; t++) {
        const int lin = tid + t * 256;       // 0..511 = (row, chunk)
        const int r = lin >> 2;
        const int c = lin & 3;
        const uint32_t so = (uint32_t)r * 64 + ((uint32_t)(c ^ ((r >> 1) & 3)) << 4);
        const size_t ga = (size_t)(mb + r) * 768 + k0 + c * 8;
        const size_t gb = (size_t)(nb + r) * 768 + k0 + c * 8;
        cpa16(sbase +     0 + so, Ahi + ga);
        cpa16(sbase +  8192 + so, Alo + ga);
        cpa16(sbase + 16384 + so, Bhi + gb);
        cpa16(sbase + 24576 + so, Blo + gb);
    }
}

__device__ __forceinline__ float epi_f(float v, float mk, int epi) {
    if (epi >= 1) v *= mk;
    if (epi == 2) { v = (v > 0.0f) ? (v + 1.0f) : expf(v); v *= 0.125f; }
    return v;
}

__global__ void __launch_bounds__(256, 2)
gemm_tc(const __nv_bfloat16* __restrict__ Ahi, const __nv_bfloat16* __restrict__ Alo,
        const __nv_bfloat16* __restrict__ Bhi, const __nv_bfloat16* __restrict__ Blo,
        const float* __restrict__ bias, const float* __restrict__ mask,
        float* __restrict__ C, int epi)
{
    extern __shared__ char smraw[];
    const uint32_t sm0 = smem_u32(smraw);

    const int tid  = threadIdx.x;
    const int lane = tid & 31;
    const int warp = tid >> 5;
    const int wm = warp & 1;        // 0..1 -> 64 rows each
    const int wn = warp >> 1;       // 0..3 -> 32 cols each
    const int nb = blockIdx.x * 128;
    const int mb = blockIdx.y * 128;

    // per-lane ldmatrix row bases (A: 4 m-tiles; B: 2 n16-tiles)
    uint32_t baseA[4], maskA[4];
    const int arow0 = wm * 64 + (lane & 15);
    const int acs   = lane >> 4;                 // chunk select 0/1
    #pragma unroll
    for (int mt = 0; mt < 4; mt++) {
        const int r = arow0 + mt * 16;
        baseA[mt] = (uint32_t)r * 64;
        maskA[mt] = (uint32_t)((r >> 1) & 3);
    }
    uint32_t baseB[2], maskB[2];
    const int brow0 = wn * 32 + (lane & 7) + ((lane >> 4) << 3);
    const int bcs   = (lane >> 3) & 1;
    #pragma unroll
    for (int bt = 0; bt < 2; bt++) {
        const int r = brow0 + bt * 16;
        baseB[bt] = (uint32_t)r * 64;
        maskB[bt] = (uint32_t)((r >> 1) & 3);
    }

    float acc[4][4][4] = {};

    stage_load(sm0, Ahi, Alo, Bhi, Blo, mb, nb, 0, tid);
    CP_COMMIT();

    #pragma unroll 1
    for (int s = 0; s < 24; s++) {
        if (s + 1 < 24) {
            stage_load(sm0 + ((s + 1) & 1) * STAGE_BYTES, Ahi, Alo, Bhi, Blo,
                       mb, nb, (s + 1) * 32, tid);
            CP_COMMIT();
            CP_WAIT(1);
        } else {
            CP_WAIT(0);
        }
        __syncthreads();

        const uint32_t sb = sm0 + (s & 1) * STAGE_BYTES;
        #pragma unroll
        for (int ks = 0; ks < 2; ks++) {
            const uint32_t kc = (uint32_t)(ks * 2);

            // B fragments (hi & lo), 4 n8-tiles
            uint32_t bh[4][2], bl[4][2];
            #pragma unroll
            for (int bt = 0; bt < 2; bt++) {
                const uint32_t off = baseB[bt] + (((kc + bcs) ^ maskB[bt]) << 4);
                uint32_t tmp[4];
                ldsm4(tmp, sb + 16384 + off);
                bh[2 * bt][0] = tmp[0]; bh[2 * bt][1] = tmp[1];
                bh[2 * bt + 1][0] = tmp[2]; bh[2 * bt + 1][1] = tmp[3];
                ldsm4(tmp, sb + 24576 + off);
                bl[2 * bt][0] = tmp[0]; bl[2 * bt][1] = tmp[1];
                bl[2 * bt + 1][0] = tmp[2]; bl[2 * bt + 1][1] = tmp[3];
            }

            // A_hi fragments, then hi*hi + hi*lo
            uint32_t a[4][4];
            #pragma unroll
            for (int mt = 0; mt < 4; mt++)
                ldsm4(a[mt], sb + baseA[mt] + (((kc + acs) ^ maskA[mt]) << 4));
            #pragma unroll
            for (int mt = 0; mt < 4; mt++)
                #pragma unroll
                for (int nt = 0; nt < 4; nt++) {
                    mma_bf16(acc[mt][nt], a[mt], bh[nt]);
                    mma_bf16(acc[mt][nt], a[mt], bl[nt]);
                }

            // A_lo fragments (reuse regs), lo*hi
            #pragma unroll
            for (int mt = 0; mt < 4; mt++)
                ldsm4(a[mt], sb + 8192 + baseA[mt] + (((kc + acs) ^ maskA[mt]) << 4));
            #pragma unroll
            for (int mt = 0; mt < 4; mt++)
                #pragma unroll
                for (int nt = 0; nt < 4; nt++)
                    mma_bf16(acc[mt][nt], a[mt], bh[nt]);
        }
        __syncthreads();
    }

    // epilogue
    const int r0 = lane >> 2;
    const int c0 = (lane & 3) * 2;
    #pragma unroll
    for (int mt = 0; mt < 4; mt++) {
        const int mrow = mb + wm * 64 + mt * 16 + r0;
        const float mk0 = (epi >= 1) ? mask[mrow] : 1.0f;
        const float mk1 = (epi >= 1) ? mask[mrow + 8] : 1.0f;
        #pragma unroll
        for (int nt = 0; nt < 4; nt++) {
            const int col = nb + wn * 32 + nt * 8 + c0;
            const float b0 = bias[col], b1 = bias[col + 1];
            float2 o0, o1;
            o0.x = epi_f(acc[mt][nt][0] + b0, mk0, epi);
            o0.y = epi_f(acc[mt][nt][1] + b1, mk0, epi);
            o1.x = epi_f(acc[mt][nt][2] + b0, mk1, epi);
            o1.y = epi_f(acc[mt][nt][3] + b1, mk1, epi);
            *reinterpret_cast<float2*>(C + (size_t)mrow * 768 + col) = o0;
            *reinterpret_cast<float2*>(C + (size_t)(mrow + 8) * 768 + col) = o1;
        }
    }
}

// ---------------------------------------------------------------------------
// Prep: split x (f32 -> bf16 hi/lo)
// ---------------------------------------------------------------------------
__global__ void __launch_bounds__(256)
split_x_kernel(const float* __restrict__ x,
               __nv_bfloat16* __restrict__ hi, __nv_bfloat16* __restrict__ lo)
{
    const size_t i = ((size_t)blockIdx.x * 256 + threadIdx.x) * 4;
    float4 v = *reinterpret_cast<const float4*>(x + i);
    const float vv[4] = {v.x, v.y, v.z, v.w};
    __nv_bfloat16 h[4], l[4];
    #pragma unroll
    for (int t = 0; t < 4; t++) {
        h[t] = __float2bfloat16(vv[t]);
        l[t] = __float2bfloat16(vv[t] - __bfloat162float(h[t]));
    }
    __nv_bfloat162* hp = reinterpret_cast<__nv_bfloat162*>(hi + i);
    __nv_bfloat162* lp = reinterpret_cast<__nv_bfloat162*>(lo + i);
    hp[0] = __halves2bfloat162(h[0], h[1]);
    hp[1] = __halves2bfloat162(h[2], h[3]);
    lp[0] = __halves2bfloat162(l[0], l[1]);
    lp[1] = __halves2bfloat162(l[2], l[3]);
}

// Prep: transpose + split W:  Wt[n][k] = W[k][n]
__global__ void __launch_bounds__(256)
wsplit_kernel(const float* __restrict__ W,
              __nv_bfloat16* __restrict__ hi, __nv_bfloat16* __restrict__ lo)
{
    __shared__ float t[32][33];
    const int bx = blockIdx.x * 32, by = blockIdx.y * 32;   // bx: n-tile, by: k-tile
    const int tx = threadIdx.x, ty = threadIdx.y;           // 32 x 8
    #pragma unroll
    for (int i = 0; i < 32; i += 8)
        t[ty + i][tx] = W[(size_t)(by + ty + i) * 768 + bx + tx];  // t[kk][nn]
    __syncthreads();
    #pragma unroll
    for (int i = 0; i < 32; i += 8) {
        const float v = t[tx][ty + i];                       // k = by+tx, n = bx+ty+i
        const __nv_bfloat16 h = __float2bfloat16(v);
        const __nv_bfloat16 l = __float2bfloat16(v - __bfloat162float(h));
        const size_t o = (size_t)(bx + ty + i) * 768 + by + tx;
        hi[o] = h; lo[o] = l;
    }
}

// ---------------------------------------------------------------------------
// Attention core (fp32)
// ---------------------------------------------------------------------------
__global__ void __launch_bounds__(256)
kv_ksum_kernel(const float* __restrict__ Kf, const float* __restrict__ Vf)
{
    __shared__ float Ks[64][64];
    __shared__ float Vs[64][64];

    const int bh = blockIdx.x;
    const int b = bh / Hh, h = bh % Hh;
    const int tid = threadIdx.x;
    const int d  = tid >> 2;
    const int e0 = (tid & 3) * 16;

    float acc[16] = {};
    float ks = 0.0f;

    for (int s0 = 0; s0 < Ss; s0 += 64) {
        #pragma unroll
        for (int i = 0; i < 4; i++) {
            const int lin = tid + i * 256;
            const int r = lin >> 4;
            const int c = (lin & 15) * 4;
            const size_t off = ((size_t)(b * Ss + s0 + r)) * 768 + h * 64 + c;
            *reinterpret_cast<float4*>(&Ks[r][c]) = *reinterpret_cast<const float4*>(Kf + off);
            *reinterpret_cast<float4*>(&Vs[r][c]) = *reinterpret_cast<const float4*>(Vf + off);
        }
        __syncthreads();

        #pragma unroll 4
        for (int s = 0; s < 64; s++) {
            const float kval = Ks[s][d];
            #pragma unroll
            for (int j = 0; j < 16; j++)
                acc[j] = fmaf(kval, Vs[s][e0 + j], acc[j]);
        }
        if (tid < 64) {
            #pragma unroll 4
            for (int s = 0; s < 64; s++) ks += Ks[s][tid];
        }
        __syncthreads();
    }

    const size_t base = ((size_t)bh * 64 + d) * 64 + e0;
    #pragma unroll
    for (int j = 0; j < 16; j++) g_kv[base + j] = acc[j];
    if (tid < 64) g_ksum[bh * 64 + tid] = ks;
}

__global__ void __launch_bounds__(256)
attn_apply_kernel(const float* __restrict__ Q,
                  __nv_bfloat16* __restrict__ Ohi, __nv_bfloat16* __restrict__ Olo)
{
    __shared__ float kvS[64][64];
    __shared__ float ksS[64];
    __shared__ float qS[4][64];

    const int bh = blockIdx.x;
    const int b = bh / Hh, h = bh % Hh;
    const int tid = threadIdx.x;

    #pragma unroll
    for (int i = 0; i < 4; i++) {
        const int lin = tid + i * 256;
        const int r = lin >> 4;
        const int c = (lin & 15) * 4;
        *reinterpret_cast<float4*>(&kvS[r][c]) =
            *reinterpret_cast<const float4*>(&g_kv[((size_t)bh * 64 + r) * 64 + c]);
    }
    if (tid < 16)
        *reinterpret_cast<float4*>(&ksS[tid * 4]) =
            *reinterpret_cast<const float4*>(&g_ksum[bh * 64 + tid * 4]);
    __syncthreads();

    const int e  = tid & 63;
    const int rr = tid >> 6;

    for (int it = 0; it < 16; it++) {
        const int s = blockIdx.y * 64 + it * 4 + rr;
        const size_t rowoff = ((size_t)(b * Ss + s)) * 768 + h * 64;
        qS[rr][e] = Q[rowoff + e];
        __syncthreads();

        float num = 0.0f, den = 0.0f;
        #pragma unroll
        for (int dd = 0; dd < 64; dd++) {
            const float qv = qS[rr][dd];
            num = fmaf(qv, kvS[dd][e], num);
            den = fmaf(qv, ksS[dd], den);
        }
        const float r = num / den;
        const __nv_bfloat16 hh = __float2bfloat16(r);
        Ohi[rowoff + e] = hh;
        Olo[rowoff + e] = __float2bfloat16(r - __bfloat162float(hh));
        __syncthreads();
    }
}

// ---------------------------------------------------------------------------
extern "C" void kernel_launch(void* const* d_in, const int* in_sizes, int n_in,
                              void* d_out, int out_size)
{
    const float* x    = (const float*)d_in[0];
    const float* mask = (const float*)d_in[1];
    const float* Wq   = (const float*)d_in[2];
    const float* bq   = (const float*)d_in[3];
    const float* Wk   = (const float*)d_in[4];
    const float* bk   = (const float*)d_in[5];
    const float* Wv   = (const float*)d_in[6];
    const float* bv   = (const float*)d_in[7];
    const float* Wo   = (const float*)d_in[8];
    const float* bo   = (const float*)d_in[9];
    float* out = (float*)d_out;

    float *qp, *kp, *vp;
    __nv_bfloat16 *xhi, *xlo, *ahi, *alo, *whi, *wlo;
    cudaGetSymbolAddress((void**)&qp,  g_q);
    cudaGetSymbolAddress((void**)&kp,  g_k);
    cudaGetSymbolAddress((void**)&vp,  g_v);
    cudaGetSymbolAddress((void**)&xhi, g_xhi);
    cudaGetSymbolAddress((void**)&xlo, g_xlo);
    cudaGetSymbolAddress((void**)&ahi, g_ahi);
    cudaGetSymbolAddress((void**)&alo, g_alo);
    cudaGetSymbolAddress((void**)&whi, g_whi);
    cudaGetSymbolAddress((void**)&wlo, g_wlo);

    cudaFuncSetAttribute(gemm_tc, cudaFuncAttributeMaxDynamicSharedMemorySize, GSMEM_BYTES);

    const size_t WSZ = 768 * 768;
    const dim3 wgrid(24, 24), wblk(32, 8);
    const dim3 ggrid(6, 512);

    // prep
    split_x_kernel<<<(int)(((size_t)M * N) / 4 / 256), 256>>>(x, xhi, xlo);
    wsplit_kernel<<<wgrid, wblk>>>(Wq, whi + 0 * WSZ, wlo + 0 * WSZ);
    wsplit_kernel<<<wgrid, wblk>>>(Wk, whi + 1 * WSZ, wlo + 1 * WSZ);
    wsplit_kernel<<<wgrid, wblk>>>(Wv, whi + 2 * WSZ, wlo + 2 * WSZ);
    wsplit_kernel<<<wgrid, wblk>>>(Wo, whi + 3 * WSZ, wlo + 3 * WSZ);

    // projections (tensor core, bf16 split)
    gemm_tc<<<ggrid, 256, GSMEM_BYTES>>>(xhi, xlo, whi + 0 * WSZ, wlo + 0 * WSZ, bq, mask, qp, 2);
    gemm_tc<<<ggrid, 256, GSMEM_BYTES>>>(xhi, xlo, whi + 1 * WSZ, wlo + 1 * WSZ, bk, mask, kp, 2);
    gemm_tc<<<ggrid, 256, GSMEM_BYTES>>>(xhi, xlo, whi + 2 * WSZ, wlo + 2 * WSZ, bv, mask, vp, 1);

    // linear-attention core (fp32)
    kv_ksum_kernel<<<Bb * Hh, 256>>>(kp, vp);
    attn_apply_kernel<<<dim3(Bb * Hh, Ss / 64), 256>>>(qp, ahi, alo);

    // output projection (tensor core, bf16 split)
    gemm_tc<<<ggrid, 256, GSMEM_BYTES>>>(ahi, alo, whi + 3 * WSZ, wlo + 3 * WSZ, bo, mask, out, 0);
}

// round 4
// speedup vs baseline: 2.3099x; 1.0379x over previous
#include <cuda_runtime.h>
#include <cuda_bf16.h>
#include <math.h>
#include <stdint.h>

// Problem constants
#define Bb   16
#define Ss   4096
#define Hh   12
#define Dd   64
constexpr int M = Bb * Ss;   // 65536
constexpr int N = 768;
constexpr int K = 768;

// ---------------------------------------------------------------------------
// Scratch (device globals)
// ---------------------------------------------------------------------------
__device__ float g_q[(size_t)M * N];
__device__ float g_k[(size_t)M * N];
__device__ float g_v[(size_t)M * N];
__device__ __nv_bfloat16 g_xhi[(size_t)M * N];
__device__ __nv_bfloat16 g_xlo[(size_t)M * N];
__device__ __nv_bfloat16 g_ahi[(size_t)M * N];
__device__ __nv_bfloat16 g_alo[(size_t)M * N];
__device__ __nv_bfloat16 g_whi[4][768 * 768];
__device__ __nv_bfloat16 g_wlo[4][768 * 768];
__device__ float g_kv[Bb * Hh * Dd * Dd];
__device__ float g_ksum[Bb * Hh * Dd];
__device__ float g_kvp[4][Bb * Hh][Dd * Dd];
__device__ float g_ksp[4][Bb * Hh][Dd];

// ---------------------------------------------------------------------------
// PTX helpers (sm_80-compatible: cp.async, ldmatrix, mma.sync)
// ---------------------------------------------------------------------------
__device__ __forceinline__ uint32_t smem_u32(const void* p) {
    uint32_t a;
    asm("{ .reg .u64 t; cvta.to.shared.u64 t, %1; cvt.u32.u64 %0, t; }"
        : "=r"(a) : "l"(p));
    return a;
}

__device__ __forceinline__ void cpa16(uint32_t dst, const void* src) {
    asm volatile("cp.async.cg.shared.global [%0], [%1], 16;" :: "r"(dst), "l"(src) : "memory");
}
#define CP_COMMIT() asm volatile("cp.async.commit_group;" ::: "memory")
#define CP_WAIT(n)  asm volatile("cp.async.wait_group %0;" :: "n"(n) : "memory")

__device__ __forceinline__ void ldsm4(uint32_t* r, uint32_t addr) {
    asm volatile("ldmatrix.sync.aligned.m8n8.x4.shared.b16 {%0,%1,%2,%3}, [%4];"
                 : "=r"(r[0]), "=r"(r[1]), "=r"(r[2]), "=r"(r[3]) : "r"(addr));
}

__device__ __forceinline__ void mma_bf16(float* c, const uint32_t* a, const uint32_t* b) {
    asm volatile(
        "mma.sync.aligned.m16n8k16.row.col.f32.bf16.bf16.f32 "
        "{%0,%1,%2,%3}, {%4,%5,%6,%7}, {%8,%9}, {%0,%1,%2,%3};"
        : "+f"(c[0]), "+f"(c[1]), "+f"(c[2]), "+f"(c[3])
        : "r"(a[0]), "r"(a[1]), "r"(a[2]), "r"(a[3]), "r"(b[0]), "r"(b[1]));
}

// ---------------------------------------------------------------------------
// bf16-split GEMM via mma.sync:
//   C[M,768] = (Ahi+Alo)[M,768] x (Whi+Wlo)^T     (W pre-transposed: Bt[n][k])
// CTA tile 128x256x32, warp tile 64x64, 3-stage cp.async pipeline.
// Smem/stage: Ahi 8K | Alo 8K | Bhi 16K | Blo 16K = 48KB. XOR swizzle on 16B
// chunks: sc = c ^ ((row>>1)&3)  (row stride 64B, 4 chunks/row).
// epi: 0 = +bias; 1 = (+bias)*mask; 2 = lka((+bias)*mask)/8
// ---------------------------------------------------------------------------
constexpr int STAGE_BYTES = 49152;
constexpr int GSMEM_BYTES = 3 * STAGE_BYTES;
constexpr int SA_HI = 0, SA_LO = 8192, SB_HI = 16384, SB_LO = 32768;

__device__ __forceinline__ void stage_load(
    uint32_t sbase,
    const __nv_bfloat16* __restrict__ Ahi, const __nv_bfloat16* __restrict__ Alo,
    const __nv_bfloat16* __restrict__ Bhi, const __nv_bfloat16* __restrict__ Blo,
    int mb, int nb, int k0, int tid)
{
    // A: 128 rows x 4 chunks = 512 slots
    #pragma unroll
    for (int t = 0; t < 2; t++) {
        const int lin = tid + t * 256;
        const int r = lin >> 2;
        const int c = lin & 3;
        const uint32_t so = (uint32_t)r * 64 + ((uint32_t)(c ^ ((r >> 1) & 3)) << 4);
        const size_t ga = (size_t)(mb + r) * 768 + k0 + c * 8;
        cpa16(sbase + SA_HI + so, Ahi + ga);
        cpa16(sbase + SA_LO + so, Alo + ga);
    }
    // B: 256 rows x 4 chunks = 1024 slots
    #pragma unroll
    for (int t = 0; t < 4; t++) {
        const int lin = tid + t * 256;
        const int r = lin >> 2;
        const int c = lin & 3;
        const uint32_t so = (uint32_t)r * 64 + ((uint32_t)(c ^ ((r >> 1) & 3)) << 4);
        const size_t gb = (size_t)(nb + r) * 768 + k0 + c * 8;
        cpa16(sbase + SB_HI + so, Bhi + gb);
        cpa16(sbase + SB_LO + so, Blo + gb);
    }
}

__device__ __forceinline__ float epi_f(float v, float mk, int epi) {
    if (epi >= 1) v *= mk;
    if (epi == 2) { v = (v > 0.0f) ? (v + 1.0f) : expf(v); v *= 0.125f; }
    return v;
}

__global__ void __launch_bounds__(256, 1)
gemm_tc(const __nv_bfloat16* __restrict__ Ahi, const __nv_bfloat16* __restrict__ Alo,
        const __nv_bfloat16* __restrict__ Bhi, const __nv_bfloat16* __restrict__ Blo,
        const float* __restrict__ bias, const float* __restrict__ mask,
        float* __restrict__ C, int epi)
{
    extern __shared__ char smraw[];
    const uint32_t sm0 = smem_u32(smraw);

    const int tid  = threadIdx.x;
    const int lane = tid & 31;
    const int warp = tid >> 5;
    const int wm = warp & 1;        // 2 warps in M -> 64 rows each
    const int wn = warp >> 1;       // 4 warps in N -> 64 cols each
    const int nb = blockIdx.x * 256;
    const int mb = blockIdx.y * 128;

    // per-lane ldmatrix addressing
    uint32_t baseA[4], maskA[4];
    const int arow0 = wm * 64 + (lane & 15);
    const uint32_t acs = (uint32_t)(lane >> 4);
    #pragma unroll
    for (int mt = 0; mt < 4; mt++) {
        const int r = arow0 + mt * 16;
        baseA[mt] = (uint32_t)r * 64;
        maskA[mt] = (uint32_t)((r >> 1) & 3);
    }
    uint32_t baseB[4], maskB[4];
    const int brow0 = wn * 64 + (lane & 7) + ((lane >> 4) << 3);
    const uint32_t bcs = (uint32_t)((lane >> 3) & 1);
    #pragma unroll
    for (int bt = 0; bt < 4; bt++) {
        const int r = brow0 + bt * 16;
        baseB[bt] = (uint32_t)r * 64;
        maskB[bt] = (uint32_t)((r >> 1) & 3);
    }

    float acc[4][8][4] = {};

    stage_load(sm0 + 0 * STAGE_BYTES, Ahi, Alo, Bhi, Blo, mb, nb, 0, tid);
    CP_COMMIT();
    stage_load(sm0 + 1 * STAGE_BYTES, Ahi, Alo, Bhi, Blo, mb, nb, 32, tid);
    CP_COMMIT();

    #pragma unroll 1
    for (int s = 0; s < 24; s++) {
        if (s < 23) { CP_WAIT(1); } else { CP_WAIT(0); }
        __syncthreads();

        const uint32_t sb = sm0 + (s % 3) * STAGE_BYTES;
        #pragma unroll
        for (int ks = 0; ks < 2; ks++) {
            const uint32_t kc = (uint32_t)(ks * 2);

            // B fragments hi & lo: 8 n8-tiles
            uint32_t bh[8][2], bl[8][2];
            #pragma unroll
            for (int bt = 0; bt < 4; bt++) {
                const uint32_t off = baseB[bt] + (((kc + bcs) ^ maskB[bt]) << 4);
                uint32_t tmp[4];
                ldsm4(tmp, sb + SB_HI + off);
                bh[2 * bt][0] = tmp[0]; bh[2 * bt][1] = tmp[1];
                bh[2 * bt + 1][0] = tmp[2]; bh[2 * bt + 1][1] = tmp[3];
                ldsm4(tmp, sb + SB_LO + off);
                bl[2 * bt][0] = tmp[0]; bl[2 * bt][1] = tmp[1];
                bl[2 * bt + 1][0] = tmp[2]; bl[2 * bt + 1][1] = tmp[3];
            }

            // A_hi, then hi*hi + hi*lo
            uint32_t a[4][4];
            #pragma unroll
            for (int mt = 0; mt < 4; mt++)
                ldsm4(a[mt], sb + SA_HI + baseA[mt] + (((kc + acs) ^ maskA[mt]) << 4));
            #pragma unroll
            for (int mt = 0; mt < 4; mt++)
                #pragma unroll
                for (int nt = 0; nt < 8; nt++) {
                    mma_bf16(acc[mt][nt], a[mt], bh[nt]);
                    mma_bf16(acc[mt][nt], a[mt], bl[nt]);
                }

            // A_lo (reuse regs), lo*hi
            #pragma unroll
            for (int mt = 0; mt < 4; mt++)
                ldsm4(a[mt], sb + SA_LO + baseA[mt] + (((kc + acs) ^ maskA[mt]) << 4));
            #pragma unroll
            for (int mt = 0; mt < 4; mt++)
                #pragma unroll
                for (int nt = 0; nt < 8; nt++)
                    mma_bf16(acc[mt][nt], a[mt], bh[nt]);
        }

        if (s + 2 < 24) {
            stage_load(sm0 + ((s + 2) % 3) * STAGE_BYTES, Ahi, Alo, Bhi, Blo,
                       mb, nb, (s + 2) * 32, tid);
            CP_COMMIT();
        }
    }

    // epilogue
    const int r0 = lane >> 2;
    const int c0 = (lane & 3) * 2;
    #pragma unroll
    for (int mt = 0; mt < 4; mt++) {
        const int mrow = mb + wm * 64 + mt * 16 + r0;
        const float mk0 = (epi >= 1) ? mask[mrow] : 1.0f;
        const float mk1 = (epi >= 1) ? mask[mrow + 8] : 1.0f;
        #pragma unroll
        for (int nt = 0; nt < 8; nt++) {
            const int col = nb + wn * 64 + nt * 8 + c0;
            const float b0 = bias[col], b1 = bias[col + 1];
            float2 o0, o1;
            o0.x = epi_f(acc[mt][nt][0] + b0, mk0, epi);
            o0.y = epi_f(acc[mt][nt][1] + b1, mk0, epi);
            o1.x = epi_f(acc[mt][nt][2] + b0, mk1, epi);
            o1.y = epi_f(acc[mt][nt][3] + b1, mk1, epi);
            *reinterpret_cast<float2*>(C + (size_t)mrow * 768 + col) = o0;
            *reinterpret_cast<float2*>(C + (size_t)(mrow + 8) * 768 + col) = o1;
        }
    }
}

// ---------------------------------------------------------------------------
// Prep: split x (f32 -> bf16 hi/lo)
// ---------------------------------------------------------------------------
__global__ void __launch_bounds__(256)
split_x_kernel(const float* __restrict__ x,
               __nv_bfloat16* __restrict__ hi, __nv_bfloat16* __restrict__ lo)
{
    const size_t i = ((size_t)blockIdx.x * 256 + threadIdx.x) * 4;
    float4 v = *reinterpret_cast<const float4*>(x + i);
    const float vv[4] = {v.x, v.y, v.z, v.w};
    __nv_bfloat16 h[4], l[4];
    #pragma unroll
    for (int t = 0; t < 4; t++) {
        h[t] = __float2bfloat16(vv[t]);
        l[t] = __float2bfloat16(vv[t] - __bfloat162float(h[t]));
    }
    __nv_bfloat162* hp = reinterpret_cast<__nv_bfloat162*>(hi + i);
    __nv_bfloat162* lp = reinterpret_cast<__nv_bfloat162*>(lo + i);
    hp[0] = __halves2bfloat162(h[0], h[1]);
    hp[1] = __halves2bfloat162(h[2], h[3]);
    lp[0] = __halves2bfloat162(l[0], l[1]);
    lp[1] = __halves2bfloat162(l[2], l[3]);
}

// Prep: transpose + split W:  Wt[n][k] = W[k][n]
__global__ void __launch_bounds__(256)
wsplit_kernel(const float* __restrict__ W,
              __nv_bfloat16* __restrict__ hi, __nv_bfloat16* __restrict__ lo)
{
    __shared__ float t[32][33];
    const int bx = blockIdx.x * 32, by = blockIdx.y * 32;
    const int tx = threadIdx.x, ty = threadIdx.y;   // 32 x 8
    #pragma unroll
    for (int i = 0; i < 32; i += 8)
        t[ty + i][tx] = W[(size_t)(by + ty + i) * 768 + bx + tx];
    __syncthreads();
    #pragma unroll
    for (int i = 0; i < 32; i += 8) {
        const float v = t[tx][ty + i];
        const __nv_bfloat16 h = __float2bfloat16(v);
        const __nv_bfloat16 l = __float2bfloat16(v - __bfloat162float(h));
        const size_t o = (size_t)(bx + ty + i) * 768 + by + tx;
        hi[o] = h; lo[o] = l;
    }
}

// ---------------------------------------------------------------------------
// Attention core (fp32): chunked kv/ksum partials + reduce, then apply
// ---------------------------------------------------------------------------
__global__ void __launch_bounds__(256)
kv_part_kernel(const float* __restrict__ Kf, const float* __restrict__ Vf)
{
    __shared__ float Ks[64][64];
    __shared__ float Vs[64][64];

    const int bh = blockIdx.x;
    const int ch = blockIdx.y;
    const int b = bh / Hh, h = bh % Hh;
    const int tid = threadIdx.x;
    const int d  = tid >> 2;
    const int e0 = (tid & 3) * 16;

    float acc[16] = {};
    float ks = 0.0f;

    const int sbeg = ch * (Ss / 4), send = sbeg + (Ss / 4);
    for (int s0 = sbeg; s0 < send; s0 += 64) {
        #pragma unroll
        for (int i = 0; i < 4; i++) {
            const int lin = tid + i * 256;
            const int r = lin >> 4;
            const int c = (lin & 15) * 4;
            const size_t off = ((size_t)(b * Ss + s0 + r)) * 768 + h * 64 + c;
            *reinterpret_cast<float4*>(&Ks[r][c]) = *reinterpret_cast<const float4*>(Kf + off);
            *reinterpret_cast<float4*>(&Vs[r][c]) = *reinterpret_cast<const float4*>(Vf + off);
        }
        __syncthreads();

        #pragma unroll 4
        for (int s = 0; s < 64; s++) {
            const float kval = Ks[s][d];
            #pragma unroll
            for (int j = 0; j < 16; j++)
                acc[j] = fmaf(kval, Vs[s][e0 + j], acc[j]);
        }
        if (tid < 64) {
            #pragma unroll 4
            for (int s = 0; s < 64; s++) ks += Ks[s][tid];
        }
        __syncthreads();
    }

    #pragma unroll
    for (int j = 0; j < 16; j++) g_kvp[ch][bh][d * 64 + e0 + j] = acc[j];
    if (tid < 64) g_ksp[ch][bh][tid] = ks;
}

__global__ void __launch_bounds__(256)
kv_reduce_kernel()
{
    const int bh = blockIdx.x;
    const int tid = threadIdx.x;
    #pragma unroll
    for (int j = 0; j < 16; j++) {
        const int idx = tid * 16 + j;
        float s = g_kvp[0][bh][idx] + g_kvp[1][bh][idx]
                + g_kvp[2][bh][idx] + g_kvp[3][bh][idx];
        g_kv[(size_t)bh * 4096 + idx] = s;
    }
    if (tid < 64) {
        g_ksum[bh * 64 + tid] = g_ksp[0][bh][tid] + g_ksp[1][bh][tid]
                              + g_ksp[2][bh][tid] + g_ksp[3][bh][tid];
    }
}

__global__ void __launch_bounds__(256)
attn_apply_kernel(const float* __restrict__ Q,
                  __nv_bfloat16* __restrict__ Ohi, __nv_bfloat16* __restrict__ Olo)
{
    __shared__ float kvS[64][64];
    __shared__ float ksS[64];
    __shared__ float qS[4][64];

    const int bh = blockIdx.x;
    const int b = bh / Hh, h = bh % Hh;
    const int tid = threadIdx.x;

    #pragma unroll
    for (int i = 0; i < 4; i++) {
        const int lin = tid + i * 256;
        const int r = lin >> 4;
        const int c = (lin & 15) * 4;
        *reinterpret_cast<float4*>(&kvS[r][c]) =
            *reinterpret_cast<const float4*>(&g_kv[((size_t)bh * 64 + r) * 64 + c]);
    }
    if (tid < 16)
        *reinterpret_cast<float4*>(&ksS[tid * 4]) =
            *reinterpret_cast<const float4*>(&g_ksum[bh * 64 + tid * 4]);
    __syncthreads();

    const int e  = tid & 63;
    const int rr = tid >> 6;

    for (int it = 0; it < 16; it++) {
        const int s = blockIdx.y * 64 + it * 4 + rr;
        const size_t rowoff = ((size_t)(b * Ss + s)) * 768 + h * 64;
        qS[rr][e] = Q[rowoff + e];
        __syncthreads();

        float num = 0.0f, den = 0.0f;
        #pragma unroll
        for (int dd = 0; dd < 64; dd++) {
            const float qv = qS[rr][dd];
            num = fmaf(qv, kvS[dd][e], num);
            den = fmaf(qv, ksS[dd], den);
        }
        const float r = num / den;
        const __nv_bfloat16 hh = __float2bfloat16(r);
        Ohi[rowoff + e] = hh;
        Olo[rowoff + e] = __float2bfloat16(r - __bfloat162float(hh));
        __syncthreads();
    }
}

// ---------------------------------------------------------------------------
extern "C" void kernel_launch(void* const* d_in, const int* in_sizes, int n_in,
                              void* d_out, int out_size)
{
    const float* x    = (const float*)d_in[0];
    const float* mask = (const float*)d_in[1];
    const float* Wq   = (const float*)d_in[2];
    const float* bq   = (const float*)d_in[3];
    const float* Wk   = (const float*)d_in[4];
    const float* bk   = (const float*)d_in[5];
    const float* Wv   = (const float*)d_in[6];
    const float* bv   = (const float*)d_in[7];
    const float* Wo   = (const float*)d_in[8];
    const float* bo   = (const float*)d_in[9];
    float* out = (float*)d_out;

    float *qp, *kp, *vp;
    __nv_bfloat16 *xhi, *xlo, *ahi, *alo, *whi, *wlo;
    cudaGetSymbolAddress((void**)&qp,  g_q);
    cudaGetSymbolAddress((void**)&kp,  g_k);
    cudaGetSymbolAddress((void**)&vp,  g_v);
    cudaGetSymbolAddress((void**)&xhi, g_xhi);
    cudaGetSymbolAddress((void**)&xlo, g_xlo);
    cudaGetSymbolAddress((void**)&ahi, g_ahi);
    cudaGetSymbolAddress((void**)&alo, g_alo);
    cudaGetSymbolAddress((void**)&whi, g_whi);
    cudaGetSymbolAddress((void**)&wlo, g_wlo);

    cudaFuncSetAttribute(gemm_tc, cudaFuncAttributeMaxDynamicSharedMemorySize, GSMEM_BYTES);

    const size_t WSZ = 768 * 768;
    const dim3 wgrid(24, 24), wblk(32, 8);
    const dim3 ggrid(3, 512);   // N/256, M/128

    // prep
    split_x_kernel<<<(int)(((size_t)M * N) / 4 / 256), 256>>>(x, xhi, xlo);
    wsplit_kernel<<<wgrid, wblk>>>(Wq, whi + 0 * WSZ, wlo + 0 * WSZ);
    wsplit_kernel<<<wgrid, wblk>>>(Wk, whi + 1 * WSZ, wlo + 1 * WSZ);
    wsplit_kernel<<<wgrid, wblk>>>(Wv, whi + 2 * WSZ, wlo + 2 * WSZ);
    wsplit_kernel<<<wgrid, wblk>>>(Wo, whi + 3 * WSZ, wlo + 3 * WSZ);

    // projections (tensor core, bf16 split)
    gemm_tc<<<ggrid, 256, GSMEM_BYTES>>>(xhi, xlo, whi + 0 * WSZ, wlo + 0 * WSZ, bq, mask, qp, 2);
    gemm_tc<<<ggrid, 256, GSMEM_BYTES>>>(xhi, xlo, whi + 1 * WSZ, wlo + 1 * WSZ, bk, mask, kp, 2);
    gemm_tc<<<ggrid, 256, GSMEM_BYTES>>>(xhi, xlo, whi + 2 * WSZ, wlo + 2 * WSZ, bv, mask, vp, 1);

    // linear-attention core (fp32)
    kv_part_kernel<<<dim3(Bb * Hh, 4), 256>>>(kp, vp);
    kv_reduce_kernel<<<Bb * Hh, 256>>>();
    attn_apply_kernel<<<dim3(Bb * Hh, Ss / 64), 256>>>(qp, ahi, alo);

    // output projection (tensor core, bf16 split)
    gemm_tc<<<ggrid, 256, GSMEM_BYTES>>>(ahi, alo, whi + 3 * WSZ, wlo + 3 * WSZ, bo, mask, out, 0);
}